// round 12
// baseline (speedup 1.0000x reference)
#include <cuda_runtime.h>
#include <cuda_fp16.h>
#include <stdint.h>
#include <math.h>

#define B_    2
#define T_    4096
#define DM    1024
#define DI    2048
#define CHK   256
#define NC    16
#define KSZ   5
#define NE    (DM*DI)
#define NPAIR 136
#define NORM_EPS 1e-6f
#define INV_C (1.0f/256.0f)

// ---------------- scratch (device globals; no allocation allowed) ----------
__device__ float   g_vu [(size_t)B_*T_*DM];     // conv+double-rms, fp32
__device__ float   g_zu [(size_t)B_*T_*DI];     // rms(z), fp32
__device__ __half  g_G  [(size_t)B_*NC*NE];     // G_k (scaled by 1/C), fp16
__device__ float   g_part[(size_t)B_*T_*DM];    // split-K partial for out
__device__ __half  g_vuT_h[(size_t)B_*DM*T_];   // vu^T fp16 [b][o][t]
__device__ __half  g_zuT_h[(size_t)B_*DI*T_];   // zu^T fp16 [b][d][t]
__device__ __half  g_zh [(size_t)B_*T_*DI];     // z fp16 [b][t][d]
__device__ __half  g_Wh [(size_t)B_*NC*NE];     // fp16(W0+dW_{k-1}) [b][k][o][d]
__device__ double  g_gram[B_*NPAIR];
__device__ double  g_w0n2;
__device__ float   g_sA[B_*NC];
__device__ float   g_sB[B_*NC];

// ---------------- mma.sync / cp.async helpers (sm_80+, NOT arch-'a') -------
__device__ __forceinline__ uint32_t smem_u32(const void* p) {
    uint32_t a;
    asm("{ .reg .u64 t; cvta.to.shared.u64 t, %1; cvt.u32.u64 %0, t; }"
        : "=r"(a) : "l"(p));
    return a;
}
__device__ __forceinline__ void ldmx4(uint32_t r[4], uint32_t addr) {
    asm volatile("ldmatrix.sync.aligned.m8n8.x4.shared.b16 {%0,%1,%2,%3}, [%4];"
        : "=r"(r[0]), "=r"(r[1]), "=r"(r[2]), "=r"(r[3]) : "r"(addr));
}
__device__ __forceinline__ void mma16816(float c[4], const uint32_t a[4],
                                         uint32_t b0, uint32_t b1) {
    asm volatile("mma.sync.aligned.m16n8k16.row.col.f32.f16.f16.f32 "
        "{%0,%1,%2,%3}, {%4,%5,%6,%7}, {%8,%9}, {%0,%1,%2,%3};"
        : "+f"(c[0]), "+f"(c[1]), "+f"(c[2]), "+f"(c[3])
        : "r"(a[0]), "r"(a[1]), "r"(a[2]), "r"(a[3]), "r"(b0), "r"(b1));
}
#define CPASYNC16(dst, src) \
    asm volatile("cp.async.cg.shared.global [%0], [%1], 16;" :: "r"(dst), "l"(src))
#define CPCOMMIT() asm volatile("cp.async.commit_group;")
#define CPWAIT(n)  asm volatile("cp.async.wait_group %0;" :: "n"(n))

// smem: A tile 128x32 fp16, B tile 256x32 fp16, row stride 80B, 4 stages
#define SROW   80
#define ATILE  (128*SROW)     // 10240
#define BTILE  (256*SROW)     // 20480
#define STGB   (ATILE+BTILE)  // 30720
#define SMEM_DYN (4*STGB)     // 122880 (4-stage)

// ---------------- GEMM mainloop: 128(M)x256(N) tile, BK=32, 256 thr, -------
// 8 warps of 64x64 (CUTLASS flagship shape), pure fp16, 4-stage cp.async ----
__device__ __forceinline__ void gemm_mainloop(
    const __half* __restrict__ A, int lda,
    const __half* __restrict__ B, int ldb,
    int K, uint32_t smb, float acc[4][8][4])
{
    int tid = threadIdx.x, lane = tid & 31, wid = tid >> 5;
    int warpM = wid & 1, warpN = wid >> 1;   // 2 x 4 warps, 64x64 each
    const int S = K / 32;

    // cp.async: A 512 chunks (2/thr), B 1024 chunks (4/thr)
    int ar0 = tid >> 2,         ac = tid & 3;
    int ar1 = (tid + 256) >> 2;
    int br  = tid >> 2;

    uint32_t aoff[4], boff[4];
#pragma unroll
    for (int mi = 0; mi < 4; mi++)
        aoff[mi] = (uint32_t)(warpM*64 + mi*16 + (lane & 15))*SROW + ((lane >> 4) & 1)*16;
#pragma unroll
    for (int bg = 0; bg < 4; bg++)
        boff[bg] = (uint32_t)(warpN*64 + bg*16 + (lane & 7) + ((lane & 16) ? 8 : 0))*SROW
                 + ((lane >> 3) & 1)*16;

    auto load_tile = [&](int s, int buf) {
        int k0 = s*32;
        uint32_t bb = smb + buf*STGB;
        CPASYNC16(bb + ar0*SROW + ac*16, A + (size_t)ar0*lda + k0 + ac*8);
        CPASYNC16(bb + ar1*SROW + ac*16, A + (size_t)ar1*lda + k0 + ac*8);
#pragma unroll
        for (int j = 0; j < 4; j++)
            CPASYNC16(bb + ATILE + (br + j*64)*SROW + ac*16,
                      B + (size_t)(br + j*64)*ldb + k0 + ac*8);
        CPCOMMIT();
    };

    load_tile(0, 0);
    if (S > 1) load_tile(1, 1);
    if (S > 2) load_tile(2, 2);

    for (int s = 0; s < S; s++) {
        if (s <= S - 3)      { CPWAIT(2); }
        else if (s == S - 2) { CPWAIT(1); }
        else                 { CPWAIT(0); }
        __syncthreads();
        if (s + 3 < S) load_tile(s + 3, (s + 3) & 3);
        uint32_t bb = smb + (s & 3)*STGB;
#pragma unroll
        for (int kk = 0; kk < 2; kk++) {
            uint32_t ah[4][4], bh[4][4];
            uint32_t kb = kk*32;
#pragma unroll
            for (int mi = 0; mi < 4; mi++)
                ldmx4(ah[mi], bb + aoff[mi] + kb);
#pragma unroll
            for (int bg = 0; bg < 4; bg++)
                ldmx4(bh[bg], bb + ATILE + boff[bg] + kb);
#pragma unroll
            for (int mi = 0; mi < 4; mi++)
#pragma unroll
                for (int ni = 0; ni < 8; ni++) {
                    int bg = ni >> 1, sub = (ni & 1)*2;
                    mma16816(acc[mi][ni], ah[mi], bh[bg][sub], bh[bg][sub+1]);
                }
        }
        __syncthreads();
    }
}

// ---------------- init ------------------------------------------------------
__global__ void zero_scalars_k() {
    int i = blockIdx.x*blockDim.x + threadIdx.x;
    if (i == 0) g_w0n2 = 0.0;
    if (i < B_*NPAIR) g_gram[i] = 0.0;
}

// ---------------- ||W0||^2 --------------------------------------------------
__global__ void w0norm_k(const float* __restrict__ W0) {
    __shared__ double sred[256];
    double s = 0.0;
    for (int i = blockIdx.x*blockDim.x + threadIdx.x; i < NE; i += gridDim.x*blockDim.x) {
        float v = W0[i];
        s += (double)v * (double)v;
    }
    sred[threadIdx.x] = s; __syncthreads();
    for (int o = 128; o > 0; o >>= 1) {
        if (threadIdx.x < o) sred[threadIdx.x] += sred[threadIdx.x + o];
        __syncthreads();
    }
    if (threadIdx.x == 0) atomicAdd(&g_w0n2, sred[0]);
}

// ---------------- causal depthwise conv + double rmsnorm -> vu (fp32) -------
__global__ void conv_vu_k(const float* __restrict__ src, const float* __restrict__ cw) {
    int bt = blockIdx.x;
    int b  = bt / T_;
    int t  = bt % T_;
    float vals[4];
    float ss = 0.f;
#pragma unroll
    for (int q = 0; q < 4; q++) {
        int o = threadIdx.x + q*256;
        float acc = 0.f;
#pragma unroll
        for (int j = 0; j < KSZ; j++) {
            int tt = t - (KSZ-1) + j;
            float x = (tt >= 0) ? src[((size_t)b*T_ + tt)*DM + o] : 0.f;
            acc = fmaf(x, cw[o*KSZ + j], acc);
        }
        vals[q] = acc;
        ss += acc*acc;
    }
    __shared__ float red[256];
    red[threadIdx.x] = ss; __syncthreads();
    for (int o = 128; o > 0; o >>= 1) {
        if (threadIdx.x < o) red[threadIdx.x] += red[threadIdx.x + o];
        __syncthreads();
    }
    float ms  = red[0] * (1.0f/DM);
    float s1  = rsqrtf(ms + NORM_EPS);
    float ms2 = ms * s1 * s1;
    float s2  = rsqrtf(ms2 + NORM_EPS);
    float s   = s1 * s2;
#pragma unroll
    for (int q = 0; q < 4; q++) {
        int o = threadIdx.x + q*256;
        g_vu[(size_t)bt*DM + o] = vals[q] * s;
    }
}

// ---------------- rmsnorm(z) -> zu (fp32) + z fp16 (fused) ------------------
__global__ void z_rms_k(const float* __restrict__ z) {
    int bt = blockIdx.x;
    const float* row = z + (size_t)bt*DI;
    float vals[8];
    float ss = 0.f;
#pragma unroll
    for (int q = 0; q < 8; q++) {
        int d = threadIdx.x + q*256;
        float v = row[d];
        vals[q] = v;
        ss += v*v;
    }
    __shared__ float red[256];
    red[threadIdx.x] = ss; __syncthreads();
    for (int o = 128; o > 0; o >>= 1) {
        if (threadIdx.x < o) red[threadIdx.x] += red[threadIdx.x + o];
        __syncthreads();
    }
    float s = rsqrtf(red[0]*(1.0f/DI) + NORM_EPS);
#pragma unroll
    for (int q = 0; q < 8; q++) {
        int d = threadIdx.x + q*256;
        float v = vals[q];
        g_zu[(size_t)bt*DI + d] = v * s;
        g_zh[(size_t)bt*DI + d] = __float2half_rn(v);
    }
}

// ---------------- transpose [b][t][W] -> [b][W][t] fp16 ---------------------
// Device globals referenced in DEVICE code only (ATS host-shadow trap).
__device__ __forceinline__ void tsplit_body(const float* __restrict__ src,
                                            __half* __restrict__ dh, int W) {
    __shared__ float tile[32][33];
    int b  = blockIdx.z;
    int w0 = blockIdx.x*32, t0 = blockIdx.y*32;
    int tid = threadIdx.x;
#pragma unroll
    for (int i = 0; i < 4; i++) {
        int q = tid + i*256; int r = q>>5, c = q&31;
        tile[r][c] = src[((size_t)b*T_ + t0 + r)*W + w0 + c];
    }
    __syncthreads();
#pragma unroll
    for (int i = 0; i < 4; i++) {
        int q = tid + i*256; int c = q>>5, r = q&31;
        size_t o = ((size_t)b*W + w0 + c)*T_ + t0 + r;
        dh[o] = __float2half_rn(tile[r][c]);
    }
}
__global__ void tsplit_vu_k() { tsplit_body(g_vu, g_vuT_h, DM); }
__global__ void tsplit_zu_k() { tsplit_body(g_zu, g_zuT_h, DI); }

// ---------------- HMMA GEMM: G[o,d] = sum_t vu[t,o] zu[t,d] / C -------------
// M=o (128 tile), N=d (256 tile), K=CHK
__global__ void __launch_bounds__(256, 1) gemmG_hmma() {
    extern __shared__ char dsm[];
    uint32_t smb = smem_u32(dsm);
    int bk = blockIdx.z;
    int b = bk >> 4, kc = bk & 15;
    int obase = blockIdx.y*128;
    int dbase = blockIdx.x*256;
    size_t abase = ((size_t)b*DM + obase)*T_ + (size_t)kc*CHK;
    size_t bbase = ((size_t)b*DI + dbase)*T_ + (size_t)kc*CHK;

    float acc[4][8][4];
#pragma unroll
    for (int i = 0; i < 4; i++)
#pragma unroll
        for (int j = 0; j < 8; j++)
#pragma unroll
            for (int r = 0; r < 4; r++) acc[i][j][r] = 0.f;

    gemm_mainloop(g_vuT_h + abase, T_, g_zuT_h + bbase, T_, CHK, smb, acc);

    int lane = threadIdx.x & 31, wid = threadIdx.x >> 5;
    int warpM = wid & 1, warpN = wid >> 1;
    int g = lane >> 2, tc = (lane & 3)*2;
    __half* Cg = g_G + (size_t)bk*NE;
#pragma unroll
    for (int mi = 0; mi < 4; mi++)
#pragma unroll
        for (int ni = 0; ni < 8; ni++) {
            int r0  = obase + warpM*64 + mi*16 + g;
            int col = dbase + warpN*64 + ni*8 + tc;
            __half2 v0 = __floats2half2_rn(acc[mi][ni][0]*INV_C, acc[mi][ni][1]*INV_C);
            __half2 v1 = __floats2half2_rn(acc[mi][ni][2]*INV_C, acc[mi][ni][3]*INV_C);
            *(__half2*)(Cg + (size_t)r0*DI + col)     = v0;
            *(__half2*)(Cg + (size_t)(r0+8)*DI + col) = v1;
        }
}

// ---------------- Gram matrix: all 136 pairwise <G_i, G_j> per batch --------
__global__ void __launch_bounds__(128, 1) gram_k() {
    int b = blockIdx.y;
    const __half* Gb = g_G + (size_t)b*NC*NE;
    float acc[NPAIR];
#pragma unroll
    for (int p = 0; p < NPAIR; p++) acc[p] = 0.f;

    for (int e = blockIdx.x*128 + threadIdx.x; e < NE; e += gridDim.x*128) {
        float g[NC];
#pragma unroll
        for (int j = 0; j < NC; j++) g[j] = __half2float(Gb[(size_t)j*NE + e]);
        int p = 0;
#pragma unroll
        for (int j = 0; j < NC; j++)
#pragma unroll
            for (int i = 0; i <= j; i++) { acc[p] = fmaf(g[i], g[j], acc[p]); p++; }
    }
    __shared__ float sw[NPAIR*4];
    int lane = threadIdx.x & 31, w = threadIdx.x >> 5;
#pragma unroll
    for (int p = 0; p < NPAIR; p++) {
        float v = acc[p];
        v += __shfl_xor_sync(0xFFFFFFFFu, v, 16);
        v += __shfl_xor_sync(0xFFFFFFFFu, v, 8);
        v += __shfl_xor_sync(0xFFFFFFFFu, v, 4);
        v += __shfl_xor_sync(0xFFFFFFFFu, v, 2);
        v += __shfl_xor_sync(0xFFFFFFFFu, v, 1);
        if (lane == 0) sw[p*4 + w] = v;
    }
    __syncthreads();
    for (int p = threadIdx.x; p < NPAIR; p += 128)
        atomicAdd(&g_gram[b*NPAIR + p],
                  (double)(sw[p*4] + sw[p*4+1] + sw[p*4+2] + sw[p*4+3]));
}

// ---------------- scalar recursion: sA_k, sB_k from Gram --------------------
__global__ void scal2_k(const float* __restrict__ lil, const float* __restrict__ ldl) {
    int b = threadIdx.x;
    if (b >= B_) return;
    double eta   = exp((double)lil[0]);
    double sg    = 1.0/(1.0 + exp(-(double)ldl[0]));
    double decay = 0.9 + (0.995 - 0.9)*sg;
    double W0n   = sqrt(g_w0n2);
    const double* Gm = g_gram + b*NPAIR;
    double beta[NC];
#pragma unroll
    for (int j = 0; j < NC; j++) beta[j] = 0.0;
    double dwn2 = 0.0;
    for (int k = 0; k < NC; k++) {
        int rb = k*(k+1)/2;
        double gn2 = Gm[rb + k];
        double gsc = fmin(0.02*W0n/(sqrt(gn2) + 1e-8), 1.0);
        double c   = (1.0 - decay)*eta*gsc;
        double dot = 0.0;
        for (int j = 0; j < k; j++) dot += beta[j]*Gm[rb + j];
        double in2 = decay*decay*dwn2 + c*c*gn2 + 2.0*decay*c*dot;
        double s   = fmin(0.1*W0n/(sqrt(in2) + 1e-8), 1.0);
        g_sA[b*NC + k] = (float)(s*decay);
        g_sB[b*NC + k] = (float)(s*c);
        for (int j = 0; j < k; j++) beta[j] *= s*decay;
        beta[k] = s*c;
        dwn2 = in2*s*s;
    }
}

// ---------------- materialize W_k = fp16(W0 + dW_{k-1}) + deltaW ------------
__global__ void matW_k(const float* __restrict__ W0, float* __restrict__ outDW) {
    int b = blockIdx.y;
    __shared__ float sA[NC], sB[NC];
    if (threadIdx.x < NC) { sA[threadIdx.x] = g_sA[b*NC + threadIdx.x];
                            sB[threadIdx.x] = g_sB[b*NC + threadIdx.x]; }
    __syncthreads();
    for (int e = blockIdx.x*blockDim.x + threadIdx.x; e < NE; e += gridDim.x*blockDim.x) {
        float w0 = W0[e];
        float dw = 0.f;
#pragma unroll
        for (int k = 0; k < NC; k++) {
            float w = w0 + dw;
            g_Wh[((size_t)b*NC + k)*NE + e] = __float2half_rn(w);
            float g = __half2float(g_G[((size_t)b*NC + k)*NE + e]);
            dw = fmaf(sA[k], dw, sB[k]*g);
        }
        outDW[(size_t)b*NE + e] = dw;
    }
}

// ---------------- HMMA GEMM: out[t,o] = z[t,:]·W_k[o,:] + bias, split-K2 ----
// M=t (128 tile), N=o (256 tile), K=DI/2 per split
__global__ void __launch_bounds__(256, 1) gemmOut_hmma(const float* __restrict__ bias,
                                                       float* __restrict__ out) {
    extern __shared__ char dsm[];
    uint32_t smb = smem_u32(dsm);
    int bz = blockIdx.z;
    int bk = bz >> 1, ks = bz & 1;          // split-K half
    int obase = blockIdx.x*256;
    int tbase = blockIdx.y*128;
    const int KH = DI/2;                     // 1024
    size_t abase = ((size_t)bk*CHK + tbase)*DI + (size_t)ks*KH;
    size_t bbase = (size_t)bk*NE + (size_t)obase*DI + (size_t)ks*KH;

    float acc[4][8][4];
#pragma unroll
    for (int i = 0; i < 4; i++)
#pragma unroll
        for (int j = 0; j < 8; j++)
#pragma unroll
            for (int r = 0; r < 4; r++) acc[i][j][r] = 0.f;

    gemm_mainloop(g_zh + abase, DI, g_Wh + bbase, DI, KH, smb, acc);

    int lane = threadIdx.x & 31, wid = threadIdx.x >> 5;
    int warpM = wid & 1, warpN = wid >> 1;
    int g = lane >> 2, tc = (lane & 3)*2;
    float* dst = (ks == 0) ? out : g_part;
#pragma unroll
    for (int mi = 0; mi < 4; mi++)
#pragma unroll
        for (int ni = 0; ni < 8; ni++) {
            int r0  = tbase + warpM*64 + mi*16 + g;
            int col = obase + warpN*64 + ni*8 + tc;
            float b0 = 0.f, b1 = 0.f;
            if (ks == 0) { b0 = bias[col]; b1 = bias[col+1]; }
            float2 v0 = make_float2(acc[mi][ni][0] + b0, acc[mi][ni][1] + b1);
            float2 v1 = make_float2(acc[mi][ni][2] + b0, acc[mi][ni][3] + b1);
            *(float2*)(dst + ((size_t)bk*CHK + r0)*DM + col)     = v0;
            *(float2*)(dst + ((size_t)bk*CHK + r0 + 8)*DM + col) = v1;
        }
}

// ---------------- split-K reduce: out += g_part ------------------------------
__global__ void addpart_k(float* __restrict__ out) {
    size_t n4 = (size_t)B_*T_*DM/4;
    float4* o4 = (float4*)out;
    for (size_t i = (size_t)blockIdx.x*blockDim.x + threadIdx.x;
         i < n4; i += (size_t)gridDim.x*blockDim.x) {
        float4 a = o4[i];
        float4 p = ((const float4*)g_part)[i];
        a.x += p.x; a.y += p.y; a.z += p.z; a.w += p.w;
        o4[i] = a;
    }
}

// ---------------- launch -----------------------------------------------------
extern "C" void kernel_launch(void* const* d_in, const int* in_sizes, int n_in,
                              void* d_out, int out_size) {
    const float* z    = (const float*)d_in[0];
    const float* src  = (const float*)d_in[1];
    const float* W0   = (const float*)d_in[2];
    const float* bias = (const float*)d_in[3];
    const float* cw   = (const float*)d_in[4];
    const float* lil  = (const float*)d_in[5];
    const float* ldl  = (const float*)d_in[6];
    float* out = (float*)d_out;

    cudaFuncSetAttribute(gemmG_hmma,   cudaFuncAttributeMaxDynamicSharedMemorySize, SMEM_DYN);
    cudaFuncSetAttribute(gemmOut_hmma, cudaFuncAttributeMaxDynamicSharedMemorySize, SMEM_DYN);

    zero_scalars_k<<<2, 256>>>();
    w0norm_k<<<256, 256>>>(W0);
    conv_vu_k<<<B_*T_, 256>>>(src, cw);
    z_rms_k<<<B_*T_, 256>>>(z);
    tsplit_vu_k<<<dim3(DM/32, T_/32, B_), 256>>>();
    tsplit_zu_k<<<dim3(DI/32, T_/32, B_), 256>>>();

    gemmG_hmma<<<dim3(DI/256, DM/128, B_*NC), 256, SMEM_DYN>>>();

    gram_k<<<dim3(512, B_), 128>>>();
    scal2_k<<<1, 32>>>(lil, ldl);
    matW_k<<<dim3(1024, B_), 256>>>(W0, out + (size_t)B_*T_*DM);

    gemmOut_hmma<<<dim3(DM/256, CHK/128, B_*NC*2), 256, SMEM_DYN>>>(bias, out);
    addpart_k<<<1024, 256>>>(out);
}

// round 15
// speedup vs baseline: 1.1244x; 1.1244x over previous
#include <cuda_runtime.h>
#include <cuda.h>
#include <cuda_fp16.h>
#include <stdint.h>
#include <math.h>

#define B_    2
#define T_    4096
#define DM    1024
#define DI    2048
#define CHK   256
#define NC    16
#define KSZ   5
#define NE    (DM*DI)
#define NPAIR 136
#define NORM_EPS 1e-6f
#define INV_C (1.0f/256.0f)

// ---------------- scratch (device globals; no allocation allowed) ----------
__device__ float   g_vu [(size_t)B_*T_*DM];     // conv+double-rms, fp32
__device__ float   g_zu [(size_t)B_*T_*DI];     // rms(z), fp32
__device__ __half  g_G  [(size_t)B_*NC*NE];     // G_k (scaled by 1/C), fp16
__device__ float   g_part[(size_t)B_*T_*DM];    // split-K partial for out
__device__ __align__(1024) __half g_vuT_h[(size_t)B_*DM*T_]; // vu^T [b][o][t]
__device__ __align__(1024) __half g_zuT_h[(size_t)B_*DI*T_]; // zu^T [b][d][t]
__device__ __align__(1024) __half g_zh [(size_t)B_*T_*DI];   // z fp16 [b][t][d]
__device__ __align__(1024) __half g_Wh [(size_t)B_*NC*NE];   // fp16 W_k [b][k][o][d]
__device__ double  g_gram[B_*NPAIR];
__device__ double  g_w0n2;
__device__ float   g_sA[B_*NC];
__device__ float   g_sB[B_*NC];

// ---------------- helpers (sm_90 baseline features, NOT arch-'a') ----------
__device__ __forceinline__ uint32_t smem_u32(const void* p) {
    uint32_t a;
    asm("{ .reg .u64 t; cvta.to.shared.u64 t, %1; cvt.u32.u64 %0, t; }"
        : "=r"(a) : "l"(p));
    return a;
}
__device__ __forceinline__ void ldmx4(uint32_t r[4], uint32_t addr) {
    asm volatile("ldmatrix.sync.aligned.m8n8.x4.shared.b16 {%0,%1,%2,%3}, [%4];"
        : "=r"(r[0]), "=r"(r[1]), "=r"(r[2]), "=r"(r[3]) : "r"(addr));
}
__device__ __forceinline__ void mma16816(float c[4], const uint32_t a[4],
                                         uint32_t b0, uint32_t b1) {
    asm volatile("mma.sync.aligned.m16n8k16.row.col.f32.f16.f16.f32 "
        "{%0,%1,%2,%3}, {%4,%5,%6,%7}, {%8,%9}, {%0,%1,%2,%3};"
        : "+f"(c[0]), "+f"(c[1]), "+f"(c[2]), "+f"(c[3])
        : "r"(a[0]), "r"(a[1]), "r"(a[2]), "r"(a[3]), "r"(b0), "r"(b1));
}
#define MBARRIER_INIT(addr, cnt) \
    asm volatile("mbarrier.init.shared.b64 [%0], %1;" \
        :: "r"((uint32_t)(addr)), "r"((uint32_t)(cnt)) : "memory")
#define MBARRIER_EXPECT_TX(addr, bytes) \
    asm volatile("mbarrier.arrive.expect_tx.shared.b64 _, [%0], %1;" \
        :: "r"((uint32_t)(addr)), "r"((uint32_t)(bytes)) : "memory")
#define MBARRIER_WAIT_PARITY(addr, parity) do { \
    uint32_t _m=(uint32_t)(addr), _p=(uint32_t)(parity), _d; \
    asm volatile("{\n\t.reg .pred p;\n\t" \
        "mbarrier.try_wait.parity.acquire.cta.shared::cta.b64 p, [%1], %2;\n\t" \
        "selp.b32 %0, 1, 0, p;\n\t}" : "=r"(_d) : "r"(_m), "r"(_p) : "memory"); \
    if (!_d) { \
        asm volatile("{\n\t.reg .pred P1;\n\t" \
            "WL_%=:\n\t" \
            "mbarrier.try_wait.parity.acquire.cta.shared::cta.b64 P1, [%0], %1, 0x989680;\n\t" \
            "@P1 bra.uni WD_%=;\n\t" \
            "bra.uni WL_%=;\n\t" \
            "WD_%=:\n\t}" :: "r"(_m), "r"(_p) : "memory"); \
    } \
} while (0)
#define FENCE_PROXY_ASYNC() \
    asm volatile("fence.proxy.async.shared::cta;" ::: "memory")
#define TMA_LOAD_2D(sm, mp, cx, cy, mbar) \
    asm volatile("cp.async.bulk.tensor.2d.shared::cta.global.tile.mbarrier::complete_tx::bytes " \
        "[%0], [%1, {%2, %3}], [%4];" \
        :: "r"((uint32_t)(sm)), "l"(mp), "r"((int)(cx)), "r"((int)(cy)), \
           "r"((uint32_t)(mbar)) : "memory")

// SW64 swizzle (matches CU_TENSOR_MAP_SWIZZLE_64B / Swizzle<2,4,3>)
#define SWZ64(x) ((x) ^ (((x) >> 3) & 0x30))

// smem: per stage A tile 128x32 fp16 (8KB) + B tile 128x32 (8KB) = 16KB; 4 stages
#define STGB   16384
#define SMEM_DYN (4*STGB + 1024)

// ---------------- GEMM mainloop: 128x128 tile, BK=32, 8 warps 64x32, -------
// pure fp16, TMA 4-stage mbarrier ring ---------------------------------------
__device__ __forceinline__ void gemm_mainloop_tma(
    const CUtensorMap* tmA, int rowA,
    const CUtensorMap* tmB, int rowB,
    int kbase, int K, uint32_t smb, uint64_t* mbar_s, float acc[4][4][4])
{
    int tid = threadIdx.x, lane = tid & 31, wid = tid >> 5;
    int warpM = wid >> 2, warpN = wid & 3;
    const int S = K / 32;

    uint32_t mb0 = smem_u32(mbar_s);
    if (tid == 0) {
#pragma unroll
        for (int i = 0; i < 4; i++) MBARRIER_INIT(mb0 + i*8, 1);
        FENCE_PROXY_ASYNC();   // order generic-proxy init before async-proxy TMA
    }
    __syncthreads();

    // unswizzled fragment offsets (64B rows); swizzle applied at use
    uint32_t aoff[4], boff[2];
#pragma unroll
    for (int mi = 0; mi < 4; mi++)
        aoff[mi] = (uint32_t)(warpM*64 + mi*16 + (lane & 15))*64 + ((lane >> 4) & 1)*16;
#pragma unroll
    for (int bg = 0; bg < 2; bg++)
        boff[bg] = (uint32_t)(warpN*32 + bg*16 + (lane & 7) + ((lane & 16) ? 8 : 0))*64
                 + ((lane >> 3) & 1)*16;

    auto issue = [&](int s) {
        int b = s & 3;
        uint32_t bb = smb + b*STGB;
        MBARRIER_EXPECT_TX(mb0 + b*8, STGB);
        TMA_LOAD_2D(bb,        tmA, kbase + s*32, rowA, mb0 + b*8);
        TMA_LOAD_2D(bb + 8192, tmB, kbase + s*32, rowB, mb0 + b*8);
    };

    if (tid == 0) { issue(0); if (S > 1) issue(1); if (S > 2) issue(2); }

    for (int s = 0; s < S; s++) {
        if (tid == 0 && s + 3 < S) issue(s + 3);   // re-arm buffer (s-1)&3
        MBARRIER_WAIT_PARITY(mb0 + (s & 3)*8, (s >> 2) & 1);
        uint32_t bb = smb + (s & 3)*STGB;
#pragma unroll
        for (int kk = 0; kk < 2; kk++) {
            uint32_t ah[4][4], bh[2][4];
            uint32_t kb = kk*32;
#pragma unroll
            for (int mi = 0; mi < 4; mi++)
                ldmx4(ah[mi], bb + SWZ64(aoff[mi] + kb));
#pragma unroll
            for (int bg = 0; bg < 2; bg++)
                ldmx4(bh[bg], bb + 8192 + SWZ64(boff[bg] + kb));
#pragma unroll
            for (int mi = 0; mi < 4; mi++)
#pragma unroll
                for (int ni = 0; ni < 4; ni++) {
                    int bg = ni >> 1, sub = (ni & 1)*2;
                    mma16816(acc[mi][ni], ah[mi], bh[bg][sub], bh[bg][sub+1]);
                }
        }
        __syncthreads();   // all warps done with buffer (s&3) before re-arm
    }
}

// ---------------- init ------------------------------------------------------
__global__ void zero_scalars_k() {
    int i = blockIdx.x*blockDim.x + threadIdx.x;
    if (i == 0) g_w0n2 = 0.0;
    if (i < B_*NPAIR) g_gram[i] = 0.0;
}

// ---------------- ||W0||^2 --------------------------------------------------
__global__ void w0norm_k(const float* __restrict__ W0) {
    __shared__ double sred[256];
    double s = 0.0;
    for (int i = blockIdx.x*blockDim.x + threadIdx.x; i < NE; i += gridDim.x*blockDim.x) {
        float v = W0[i];
        s += (double)v * (double)v;
    }
    sred[threadIdx.x] = s; __syncthreads();
    for (int o = 128; o > 0; o >>= 1) {
        if (threadIdx.x < o) sred[threadIdx.x] += sred[threadIdx.x + o];
        __syncthreads();
    }
    if (threadIdx.x == 0) atomicAdd(&g_w0n2, sred[0]);
}

// ---------------- causal depthwise conv + double rmsnorm -> vu (fp32) -------
__global__ void conv_vu_k(const float* __restrict__ src, const float* __restrict__ cw) {
    int bt = blockIdx.x;
    int b  = bt / T_;
    int t  = bt % T_;
    float vals[4];
    float ss = 0.f;
#pragma unroll
    for (int q = 0; q < 4; q++) {
        int o = threadIdx.x + q*256;
        float acc = 0.f;
#pragma unroll
        for (int j = 0; j < KSZ; j++) {
            int tt = t - (KSZ-1) + j;
            float x = (tt >= 0) ? src[((size_t)b*T_ + tt)*DM + o] : 0.f;
            acc = fmaf(x, cw[o*KSZ + j], acc);
        }
        vals[q] = acc;
        ss += acc*acc;
    }
    __shared__ float red[256];
    red[threadIdx.x] = ss; __syncthreads();
    for (int o = 128; o > 0; o >>= 1) {
        if (threadIdx.x < o) red[threadIdx.x] += red[threadIdx.x + o];
        __syncthreads();
    }
    float ms  = red[0] * (1.0f/DM);
    float s1  = rsqrtf(ms + NORM_EPS);
    float ms2 = ms * s1 * s1;
    float s2  = rsqrtf(ms2 + NORM_EPS);
    float s   = s1 * s2;
#pragma unroll
    for (int q = 0; q < 4; q++) {
        int o = threadIdx.x + q*256;
        g_vu[(size_t)bt*DM + o] = vals[q] * s;
    }
}

// ---------------- rmsnorm(z) -> zu (fp32) + z fp16 (fused) ------------------
__global__ void z_rms_k(const float* __restrict__ z) {
    int bt = blockIdx.x;
    const float* row = z + (size_t)bt*DI;
    float vals[8];
    float ss = 0.f;
#pragma unroll
    for (int q = 0; q < 8; q++) {
        int d = threadIdx.x + q*256;
        float v = row[d];
        vals[q] = v;
        ss += v*v;
    }
    __shared__ float red[256];
    red[threadIdx.x] = ss; __syncthreads();
    for (int o = 128; o > 0; o >>= 1) {
        if (threadIdx.x < o) red[threadIdx.x] += red[threadIdx.x + o];
        __syncthreads();
    }
    float s = rsqrtf(red[0]*(1.0f/DI) + NORM_EPS);
#pragma unroll
    for (int q = 0; q < 8; q++) {
        int d = threadIdx.x + q*256;
        float v = vals[q];
        g_zu[(size_t)bt*DI + d] = v * s;
        g_zh[(size_t)bt*DI + d] = __float2half_rn(v);
    }
}

// ---------------- transpose [b][t][W] -> [b][W][t] fp16 ---------------------
// Device globals referenced in DEVICE code only (ATS host-shadow trap).
__device__ __forceinline__ void tsplit_body(const float* __restrict__ src,
                                            __half* __restrict__ dh, int W) {
    __shared__ float tile[32][33];
    int b  = blockIdx.z;
    int w0 = blockIdx.x*32, t0 = blockIdx.y*32;
    int tid = threadIdx.x;
#pragma unroll
    for (int i = 0; i < 4; i++) {
        int q = tid + i*256; int r = q>>5, c = q&31;
        tile[r][c] = src[((size_t)b*T_ + t0 + r)*W + w0 + c];
    }
    __syncthreads();
#pragma unroll
    for (int i = 0; i < 4; i++) {
        int q = tid + i*256; int c = q>>5, r = q&31;
        size_t o = ((size_t)b*W + w0 + c)*T_ + t0 + r;
        dh[o] = __float2half_rn(tile[r][c]);
    }
}
__global__ void tsplit_vu_k() { tsplit_body(g_vu, g_vuT_h, DM); }
__global__ void tsplit_zu_k() { tsplit_body(g_zu, g_zuT_h, DI); }

// ---------------- HMMA GEMM (TMA): G[o,d] = sum_t vu[t,o] zu[t,d] / C -------
__global__ void __launch_bounds__(256, 2) gemmG_hmma(
    const __grid_constant__ CUtensorMap tmA,
    const __grid_constant__ CUtensorMap tmB)
{
    extern __shared__ char dsm[];
    __shared__ uint64_t mbar_s[4];
    uint32_t dyn0 = smem_u32(dsm);
    uint32_t smb  = (dyn0 + 1023u) & ~1023u;
    int bk = blockIdx.z;
    int b = bk >> 4, kc = bk & 15;
    int obase = blockIdx.y*128;
    int dbase = blockIdx.x*128;

    float acc[4][4][4];
#pragma unroll
    for (int i = 0; i < 4; i++)
#pragma unroll
        for (int j = 0; j < 4; j++)
#pragma unroll
            for (int r = 0; r < 4; r++) acc[i][j][r] = 0.f;

    gemm_mainloop_tma(&tmA, b*DM + obase, &tmB, b*DI + dbase,
                      kc*CHK, CHK, smb, mbar_s, acc);

    int lane = threadIdx.x & 31, wid = threadIdx.x >> 5;
    int warpM = wid >> 2, warpN = wid & 3;
    int g = lane >> 2, tc = (lane & 3)*2;
    __half* Cg = g_G + (size_t)bk*NE;
#pragma unroll
    for (int mi = 0; mi < 4; mi++)
#pragma unroll
        for (int ni = 0; ni < 4; ni++) {
            int r0  = obase + warpM*64 + mi*16 + g;
            int col = dbase + warpN*32 + ni*8 + tc;
            __half2 v0 = __floats2half2_rn(acc[mi][ni][0]*INV_C, acc[mi][ni][1]*INV_C);
            __half2 v1 = __floats2half2_rn(acc[mi][ni][2]*INV_C, acc[mi][ni][3]*INV_C);
            *(__half2*)(Cg + (size_t)r0*DI + col)     = v0;
            *(__half2*)(Cg + (size_t)(r0+8)*DI + col) = v1;
        }
}

// ---------------- Gram matrix: all 136 pairwise <G_i, G_j> per batch --------
__global__ void __launch_bounds__(128, 1) gram_k() {
    int b = blockIdx.y;
    const __half* Gb = g_G + (size_t)b*NC*NE;
    float acc[NPAIR];
#pragma unroll
    for (int p = 0; p < NPAIR; p++) acc[p] = 0.f;

    for (int e = blockIdx.x*128 + threadIdx.x; e < NE; e += gridDim.x*128) {
        float g[NC];
#pragma unroll
        for (int j = 0; j < NC; j++) g[j] = __half2float(Gb[(size_t)j*NE + e]);
        int p = 0;
#pragma unroll
        for (int j = 0; j < NC; j++)
#pragma unroll
            for (int i = 0; i <= j; i++) { acc[p] = fmaf(g[i], g[j], acc[p]); p++; }
    }
    __shared__ float sw[NPAIR*4];
    int lane = threadIdx.x & 31, w = threadIdx.x >> 5;
#pragma unroll
    for (int p = 0; p < NPAIR; p++) {
        float v = acc[p];
        v += __shfl_xor_sync(0xFFFFFFFFu, v, 16);
        v += __shfl_xor_sync(0xFFFFFFFFu, v, 8);
        v += __shfl_xor_sync(0xFFFFFFFFu, v, 4);
        v += __shfl_xor_sync(0xFFFFFFFFu, v, 2);
        v += __shfl_xor_sync(0xFFFFFFFFu, v, 1);
        if (lane == 0) sw[p*4 + w] = v;
    }
    __syncthreads();
    for (int p = threadIdx.x; p < NPAIR; p += 128)
        atomicAdd(&g_gram[b*NPAIR + p],
                  (double)(sw[p*4] + sw[p*4+1] + sw[p*4+2] + sw[p*4+3]));
}

// ---------------- scalar recursion: sA_k, sB_k from Gram --------------------
__global__ void scal2_k(const float* __restrict__ lil, const float* __restrict__ ldl) {
    int b = threadIdx.x;
    if (b >= B_) return;
    double eta   = exp((double)lil[0]);
    double sg    = 1.0/(1.0 + exp(-(double)ldl[0]));
    double decay = 0.9 + (0.995 - 0.9)*sg;
    double W0n   = sqrt(g_w0n2);
    const double* Gm = g_gram + b*NPAIR;
    double beta[NC];
#pragma unroll
    for (int j = 0; j < NC; j++) beta[j] = 0.0;
    double dwn2 = 0.0;
    for (int k = 0; k < NC; k++) {
        int rb = k*(k+1)/2;
        double gn2 = Gm[rb + k];
        double gsc = fmin(0.02*W0n/(sqrt(gn2) + 1e-8), 1.0);
        double c   = (1.0 - decay)*eta*gsc;
        double dot = 0.0;
        for (int j = 0; j < k; j++) dot += beta[j]*Gm[rb + j];
        double in2 = decay*decay*dwn2 + c*c*gn2 + 2.0*decay*c*dot;
        double s   = fmin(0.1*W0n/(sqrt(in2) + 1e-8), 1.0);
        g_sA[b*NC + k] = (float)(s*decay);
        g_sB[b*NC + k] = (float)(s*c);
        for (int j = 0; j < k; j++) beta[j] *= s*decay;
        beta[k] = s*c;
        dwn2 = in2*s*s;
    }
}

// ---------------- materialize W_k = fp16(W0 + dW_{k-1}) + deltaW ------------
__global__ void matW_k(const float* __restrict__ W0, float* __restrict__ outDW) {
    int b = blockIdx.y;
    __shared__ float sA[NC], sB[NC];
    if (threadIdx.x < NC) { sA[threadIdx.x] = g_sA[b*NC + threadIdx.x];
                            sB[threadIdx.x] = g_sB[b*NC + threadIdx.x]; }
    __syncthreads();
    for (int e = blockIdx.x*blockDim.x + threadIdx.x; e < NE; e += gridDim.x*blockDim.x) {
        float w0 = W0[e];
        float dw = 0.f;
#pragma unroll
        for (int k = 0; k < NC; k++) {
            float w = w0 + dw;
            g_Wh[((size_t)b*NC + k)*NE + e] = __float2half_rn(w);
            float g = __half2float(g_G[((size_t)b*NC + k)*NE + e]);
            dw = fmaf(sA[k], dw, sB[k]*g);
        }
        outDW[(size_t)b*NE + e] = dw;
    }
}

// ---------------- HMMA GEMM (TMA): out = z·W_k^T + bias, split-K2 -----------
__global__ void __launch_bounds__(256, 2) gemmOut_hmma(
    const __grid_constant__ CUtensorMap tmA,
    const __grid_constant__ CUtensorMap tmB,
    const float* __restrict__ bias, float* __restrict__ out)
{
    extern __shared__ char dsm[];
    __shared__ uint64_t mbar_s[4];
    uint32_t dyn0 = smem_u32(dsm);
    uint32_t smb  = (dyn0 + 1023u) & ~1023u;
    int bz = blockIdx.z;
    int bk = bz >> 1, ks = bz & 1;
    int obase = blockIdx.x*128;
    int tbase = blockIdx.y*128;
    const int KH = DI/2;

    float acc[4][4][4];
#pragma unroll
    for (int i = 0; i < 4; i++)
#pragma unroll
        for (int j = 0; j < 4; j++)
#pragma unroll
            for (int r = 0; r < 4; r++) acc[i][j][r] = 0.f;

    gemm_mainloop_tma(&tmA, bk*CHK + tbase, &tmB, bk*DM + obase,
                      ks*KH, KH, smb, mbar_s, acc);

    int lane = threadIdx.x & 31, wid = threadIdx.x >> 5;
    int warpM = wid >> 2, warpN = wid & 3;
    int g = lane >> 2, tc = (lane & 3)*2;
    float* dst = (ks == 0) ? out : g_part;
#pragma unroll
    for (int mi = 0; mi < 4; mi++)
#pragma unroll
        for (int ni = 0; ni < 4; ni++) {
            int r0  = tbase + warpM*64 + mi*16 + g;
            int col = obase + warpN*32 + ni*8 + tc;
            float b0 = 0.f, b1 = 0.f;
            if (ks == 0) { b0 = bias[col]; b1 = bias[col+1]; }
            float2 v0 = make_float2(acc[mi][ni][0] + b0, acc[mi][ni][1] + b1);
            float2 v1 = make_float2(acc[mi][ni][2] + b0, acc[mi][ni][3] + b1);
            *(float2*)(dst + ((size_t)bk*CHK + r0)*DM + col)     = v0;
            *(float2*)(dst + ((size_t)bk*CHK + r0 + 8)*DM + col) = v1;
        }
}

// ---------------- split-K reduce: out += g_part ------------------------------
__global__ void addpart_k(float* __restrict__ out) {
    size_t n4 = (size_t)B_*T_*DM/4;
    float4* o4 = (float4*)out;
    for (size_t i = (size_t)blockIdx.x*blockDim.x + threadIdx.x;
         i < n4; i += (size_t)gridDim.x*blockDim.x) {
        float4 a = o4[i];
        float4 p = ((const float4*)g_part)[i];
        a.x += p.x; a.y += p.y; a.z += p.z; a.w += p.w;
        o4[i] = a;
    }
}

// ---------------- host: tensor map builder (runtime-resolved driver API) ----
typedef CUresult (*EncFn)(CUtensorMap*, CUtensorMapDataType, cuuint32_t, void*,
                          const cuuint64_t*, const cuuint64_t*, const cuuint32_t*,
                          const cuuint32_t*, CUtensorMapInterleave, CUtensorMapSwizzle,
                          CUtensorMapL2promotion, CUtensorMapFloatOOBfill);

static EncFn get_enc() {
    static EncFn fn = nullptr;
    if (!fn) {
        void* p = nullptr;
        cudaDriverEntryPointQueryResult st;
        cudaGetDriverEntryPoint("cuTensorMapEncodeTiled", &p, cudaEnableDefault, &st);
        fn = (EncFn)p;
    }
    return fn;
}

static void enc_map(CUtensorMap* m, void* base, uint64_t klen, uint64_t nrows) {
    cuuint64_t dims[2]    = {klen, nrows};
    cuuint64_t strides[1] = {klen * 2};       // bytes, multiple of 16
    cuuint32_t box[2]     = {32, 128};        // 64B x 128 rows
    cuuint32_t es[2]      = {1, 1};
    get_enc()(m, CU_TENSOR_MAP_DATA_TYPE_FLOAT16, 2, base,
        dims, strides, box, es, CU_TENSOR_MAP_INTERLEAVE_NONE,
        CU_TENSOR_MAP_SWIZZLE_64B, CU_TENSOR_MAP_L2_PROMOTION_L2_128B,
        CU_TENSOR_MAP_FLOAT_OOB_FILL_NONE);
}

// ---------------- launch -----------------------------------------------------
extern "C" void kernel_launch(void* const* d_in, const int* in_sizes, int n_in,
                              void* d_out, int out_size) {
    const float* z    = (const float*)d_in[0];
    const float* src  = (const float*)d_in[1];
    const float* W0   = (const float*)d_in[2];
    const float* bias = (const float*)d_in[3];
    const float* cw   = (const float*)d_in[4];
    const float* lil  = (const float*)d_in[5];
    const float* ldl  = (const float*)d_in[6];
    float* out = (float*)d_out;

    cudaFuncSetAttribute(gemmG_hmma,   cudaFuncAttributeMaxDynamicSharedMemorySize, SMEM_DYN);
    cudaFuncSetAttribute(gemmOut_hmma, cudaFuncAttributeMaxDynamicSharedMemorySize, SMEM_DYN);

    // tensor maps (pure host-side; identical every call -> capture-safe)
    void *p_vuT, *p_zuT, *p_zh, *p_Wh;
    cudaGetSymbolAddress(&p_vuT, g_vuT_h);
    cudaGetSymbolAddress(&p_zuT, g_zuT_h);
    cudaGetSymbolAddress(&p_zh,  g_zh);
    cudaGetSymbolAddress(&p_Wh,  g_Wh);
    CUtensorMap tmVu, tmZu, tmZ, tmW;
    enc_map(&tmVu, p_vuT, T_, (uint64_t)B_*DM);
    enc_map(&tmZu, p_zuT, T_, (uint64_t)B_*DI);
    enc_map(&tmZ,  p_zh,  DI, (uint64_t)B_*T_);
    enc_map(&tmW,  p_Wh,  DI, (uint64_t)B_*NC*DM);

    zero_scalars_k<<<2, 256>>>();
    w0norm_k<<<256, 256>>>(W0);
    conv_vu_k<<<B_*T_, 256>>>(src, cw);
    z_rms_k<<<B_*T_, 256>>>(z);
    tsplit_vu_k<<<dim3(DM/32, T_/32, B_), 256>>>();
    tsplit_zu_k<<<dim3(DI/32, T_/32, B_), 256>>>();

    gemmG_hmma<<<dim3(DI/128, DM/128, B_*NC), 256, SMEM_DYN>>>(tmVu, tmZu);

    gram_k<<<dim3(512, B_), 128>>>();
    scal2_k<<<1, 32>>>(lil, ldl);
    matW_k<<<dim3(1024, B_), 256>>>(W0, out + (size_t)B_*T_*DM);

    gemmOut_hmma<<<dim3(DM/128, CHK/128, B_*NC*2), 256, SMEM_DYN>>>(tmZ, tmW, bias, out);
    addpart_k<<<1024, 256>>>(out);
}

// round 17
// speedup vs baseline: 1.1499x; 1.0227x over previous
#include <cuda_runtime.h>
#include <cuda.h>
#include <cuda_fp16.h>
#include <stdint.h>
#include <math.h>

#define B_    2
#define T_    4096
#define DM    1024
#define DI    2048
#define CHK   256
#define NC    16
#define KSZ   5
#define NE    (DM*DI)
#define NPAIR 136
#define NORM_EPS 1e-6f
#define INV_C (1.0f/256.0f)

// ---------------- scratch (device globals; no allocation allowed) ----------
__device__ float   g_vu [(size_t)B_*T_*DM];     // conv+double-rms, fp32
__device__ float   g_zu [(size_t)B_*T_*DI];     // rms(z), fp32
__device__ __half  g_G  [(size_t)B_*NC*NE];     // G_k (scaled by 1/C), fp16
__device__ float   g_part[(size_t)B_*T_*DM];    // split-K partial for out
__device__ __align__(1024) __half g_vuT_h[(size_t)B_*DM*T_]; // vu^T [b][o][t]
__device__ __align__(1024) __half g_zuT_h[(size_t)B_*DI*T_]; // zu^T [b][d][t]
__device__ __align__(1024) __half g_zh [(size_t)B_*T_*DI];   // z fp16 [b][t][d]
__device__ __align__(1024) __half g_Wh [(size_t)B_*NC*NE];   // fp16 W_k [b][k][o][d]
__device__ double  g_gram[B_*NPAIR];
__device__ double  g_w0n2;
__device__ float   g_sA[B_*NC];
__device__ float   g_sB[B_*NC];

// ---------------- helpers (sm_90 baseline features, NOT arch-'a') ----------
__device__ __forceinline__ uint32_t smem_u32(const void* p) {
    uint32_t a;
    asm("{ .reg .u64 t; cvta.to.shared.u64 t, %1; cvt.u32.u64 %0, t; }"
        : "=r"(a) : "l"(p));
    return a;
}
__device__ __forceinline__ void ldmx4(uint32_t r[4], uint32_t addr) {
    asm volatile("ldmatrix.sync.aligned.m8n8.x4.shared.b16 {%0,%1,%2,%3}, [%4];"
        : "=r"(r[0]), "=r"(r[1]), "=r"(r[2]), "=r"(r[3]) : "r"(addr));
}
__device__ __forceinline__ void mma16816(float c[4], const uint32_t a[4],
                                         uint32_t b0, uint32_t b1) {
    asm volatile("mma.sync.aligned.m16n8k16.row.col.f32.f16.f16.f32 "
        "{%0,%1,%2,%3}, {%4,%5,%6,%7}, {%8,%9}, {%0,%1,%2,%3};"
        : "+f"(c[0]), "+f"(c[1]), "+f"(c[2]), "+f"(c[3])
        : "r"(a[0]), "r"(a[1]), "r"(a[2]), "r"(a[3]), "r"(b0), "r"(b1));
}
#define MBARRIER_INIT(addr, cnt) \
    asm volatile("mbarrier.init.shared.b64 [%0], %1;" \
        :: "r"((uint32_t)(addr)), "r"((uint32_t)(cnt)) : "memory")
#define MBARRIER_EXPECT_TX(addr, bytes) \
    asm volatile("mbarrier.arrive.expect_tx.shared.b64 _, [%0], %1;" \
        :: "r"((uint32_t)(addr)), "r"((uint32_t)(bytes)) : "memory")
#define MBARRIER_WAIT_PARITY(addr, parity) do { \
    uint32_t _m=(uint32_t)(addr), _p=(uint32_t)(parity), _d; \
    asm volatile("{\n\t.reg .pred p;\n\t" \
        "mbarrier.try_wait.parity.acquire.cta.shared::cta.b64 p, [%1], %2;\n\t" \
        "selp.b32 %0, 1, 0, p;\n\t}" : "=r"(_d) : "r"(_m), "r"(_p) : "memory"); \
    if (!_d) { \
        asm volatile("{\n\t.reg .pred P1;\n\t" \
            "WL_%=:\n\t" \
            "mbarrier.try_wait.parity.acquire.cta.shared::cta.b64 P1, [%0], %1, 0x989680;\n\t" \
            "@P1 bra.uni WD_%=;\n\t" \
            "bra.uni WL_%=;\n\t" \
            "WD_%=:\n\t}" :: "r"(_m), "r"(_p) : "memory"); \
    } \
} while (0)
#define FENCE_PROXY_ASYNC() \
    asm volatile("fence.proxy.async.shared::cta;" ::: "memory")
#define TMA_LOAD_2D(sm, mp, cx, cy, mbar) \
    asm volatile("cp.async.bulk.tensor.2d.shared::cta.global.tile.mbarrier::complete_tx::bytes " \
        "[%0], [%1, {%2, %3}], [%4];" \
        :: "r"((uint32_t)(sm)), "l"(mp), "r"((int)(cx)), "r"((int)(cy)), \
           "r"((uint32_t)(mbar)) : "memory")

// SW128 swizzle (matches CU_TENSOR_MAP_SWIZZLE_128B with 128-byte rows)
#define SWZ128(x) ((x) ^ (((x) >> 3) & 0x70))

// smem: per stage A tile 128x64 fp16 (16KB) + B tile 128x64 (16KB) = 32KB; 3 stages
#define TILEB  16384
#define STGB   (2*TILEB)
#define SMEM_DYN (3*STGB + 1024)

// ---------------- GEMM mainloop: 128x128 tile, BK=64, 8 warps 64x32, -------
// pure fp16, TMA 3-stage mbarrier ring ---------------------------------------
__device__ __forceinline__ void gemm_mainloop_tma(
    const CUtensorMap* tmA, int rowA,
    const CUtensorMap* tmB, int rowB,
    int kbase, int K, uint32_t smb, uint64_t* mbar_s, float acc[4][4][4])
{
    int tid = threadIdx.x, lane = tid & 31, wid = tid >> 5;
    int warpM = wid >> 2, warpN = wid & 3;
    const int S = K / 64;

    uint32_t mb0 = smem_u32(mbar_s);
    if (tid == 0) {
#pragma unroll
        for (int i = 0; i < 3; i++) MBARRIER_INIT(mb0 + i*8, 1);
        FENCE_PROXY_ASYNC();   // order generic-proxy init before async-proxy TMA
    }
    __syncthreads();

    // unswizzled fragment offsets (128B rows); swizzle applied at use
    uint32_t aoff[4], boff[2];
#pragma unroll
    for (int mi = 0; mi < 4; mi++)
        aoff[mi] = (uint32_t)(warpM*64 + mi*16 + (lane & 15))*128 + ((lane >> 4) & 1)*16;
#pragma unroll
    for (int bg = 0; bg < 2; bg++)
        boff[bg] = (uint32_t)(warpN*32 + bg*16 + (lane & 7) + ((lane & 16) ? 8 : 0))*128
                 + ((lane >> 3) & 1)*16;

    auto issue = [&](int s) {
        int b = s % 3;
        uint32_t bb = smb + b*STGB;
        MBARRIER_EXPECT_TX(mb0 + b*8, STGB);
        TMA_LOAD_2D(bb,         tmA, kbase + s*64, rowA, mb0 + b*8);
        TMA_LOAD_2D(bb + TILEB, tmB, kbase + s*64, rowB, mb0 + b*8);
    };

    if (tid == 0) { issue(0); if (S > 1) issue(1); if (S > 2) issue(2); }

    for (int s = 0; s < S; s++) {
        int b = s % 3;
        MBARRIER_WAIT_PARITY(mb0 + b*8, (s/3) & 1);
        uint32_t bb = smb + b*STGB;
#pragma unroll
        for (int kk = 0; kk < 4; kk++) {
            uint32_t ah[4][4], bh[2][4];
            uint32_t kb = kk*32;
#pragma unroll
            for (int mi = 0; mi < 4; mi++)
                ldmx4(ah[mi], bb + SWZ128(aoff[mi] + kb));
#pragma unroll
            for (int bg = 0; bg < 2; bg++)
                ldmx4(bh[bg], bb + TILEB + SWZ128(boff[bg] + kb));
#pragma unroll
            for (int mi = 0; mi < 4; mi++)
#pragma unroll
                for (int ni = 0; ni < 4; ni++) {
                    int bg = ni >> 1, sub = (ni & 1)*2;
                    mma16816(acc[mi][ni], ah[mi], bh[bg][sub], bh[bg][sub+1]);
                }
        }
        __syncthreads();                       // buffer b free across all warps
        if (tid == 0 && s + 3 < S) issue(s + 3);  // re-arm it for stage s+3
    }
}

// ---------------- init ------------------------------------------------------
__global__ void zero_scalars_k() {
    int i = blockIdx.x*blockDim.x + threadIdx.x;
    if (i == 0) g_w0n2 = 0.0;
    if (i < B_*NPAIR) g_gram[i] = 0.0;
}

// ---------------- ||W0||^2 --------------------------------------------------
__global__ void w0norm_k(const float* __restrict__ W0) {
    __shared__ double sred[256];
    double s = 0.0;
    for (int i = blockIdx.x*blockDim.x + threadIdx.x; i < NE; i += gridDim.x*blockDim.x) {
        float v = W0[i];
        s += (double)v * (double)v;
    }
    sred[threadIdx.x] = s; __syncthreads();
    for (int o = 128; o > 0; o >>= 1) {
        if (threadIdx.x < o) sred[threadIdx.x] += sred[threadIdx.x + o];
        __syncthreads();
    }
    if (threadIdx.x == 0) atomicAdd(&g_w0n2, sred[0]);
}

// ---------------- causal depthwise conv + double rmsnorm -> vu (fp32) -------
__global__ void conv_vu_k(const float* __restrict__ src, const float* __restrict__ cw) {
    int bt = blockIdx.x;
    int b  = bt / T_;
    int t  = bt % T_;
    float vals[4];
    float ss = 0.f;
#pragma unroll
    for (int q = 0; q < 4; q++) {
        int o = threadIdx.x + q*256;
        float acc = 0.f;
#pragma unroll
        for (int j = 0; j < KSZ; j++) {
            int tt = t - (KSZ-1) + j;
            float x = (tt >= 0) ? src[((size_t)b*T_ + tt)*DM + o] : 0.f;
            acc = fmaf(x, cw[o*KSZ + j], acc);
        }
        vals[q] = acc;
        ss += acc*acc;
    }
    __shared__ float red[256];
    red[threadIdx.x] = ss; __syncthreads();
    for (int o = 128; o > 0; o >>= 1) {
        if (threadIdx.x < o) red[threadIdx.x] += red[threadIdx.x + o];
        __syncthreads();
    }
    float ms  = red[0] * (1.0f/DM);
    float s1  = rsqrtf(ms + NORM_EPS);
    float ms2 = ms * s1 * s1;
    float s2  = rsqrtf(ms2 + NORM_EPS);
    float s   = s1 * s2;
#pragma unroll
    for (int q = 0; q < 4; q++) {
        int o = threadIdx.x + q*256;
        g_vu[(size_t)bt*DM + o] = vals[q] * s;
    }
}

// ---------------- rmsnorm(z) -> zu (fp32) + z fp16 (fused) ------------------
__global__ void z_rms_k(const float* __restrict__ z) {
    int bt = blockIdx.x;
    const float* row = z + (size_t)bt*DI;
    float vals[8];
    float ss = 0.f;
#pragma unroll
    for (int q = 0; q < 8; q++) {
        int d = threadIdx.x + q*256;
        float v = row[d];
        vals[q] = v;
        ss += v*v;
    }
    __shared__ float red[256];
    red[threadIdx.x] = ss; __syncthreads();
    for (int o = 128; o > 0; o >>= 1) {
        if (threadIdx.x < o) red[threadIdx.x] += red[threadIdx.x + o];
        __syncthreads();
    }
    float s = rsqrtf(red[0]*(1.0f/DI) + NORM_EPS);
#pragma unroll
    for (int q = 0; q < 8; q++) {
        int d = threadIdx.x + q*256;
        float v = vals[q];
        g_zu[(size_t)bt*DI + d] = v * s;
        g_zh[(size_t)bt*DI + d] = __float2half_rn(v);
    }
}

// ---------------- transpose [b][t][W] -> [b][W][t] fp16 ---------------------
// Device globals referenced in DEVICE code only (ATS host-shadow trap).
__device__ __forceinline__ void tsplit_body(const float* __restrict__ src,
                                            __half* __restrict__ dh, int W) {
    __shared__ float tile[32][33];
    int b  = blockIdx.z;
    int w0 = blockIdx.x*32, t0 = blockIdx.y*32;
    int tid = threadIdx.x;
#pragma unroll
    for (int i = 0; i < 4; i++) {
        int q = tid + i*256; int r = q>>5, c = q&31;
        tile[r][c] = src[((size_t)b*T_ + t0 + r)*W + w0 + c];
    }
    __syncthreads();
#pragma unroll
    for (int i = 0; i < 4; i++) {
        int q = tid + i*256; int c = q>>5, r = q&31;
        size_t o = ((size_t)b*W + w0 + c)*T_ + t0 + r;
        dh[o] = __float2half_rn(tile[r][c]);
    }
}
__global__ void tsplit_vu_k() { tsplit_body(g_vu, g_vuT_h, DM); }
__global__ void tsplit_zu_k() { tsplit_body(g_zu, g_zuT_h, DI); }

// ---------------- HMMA GEMM (TMA): G[o,d] = sum_t vu[t,o] zu[t,d] / C -------
__global__ void __launch_bounds__(256, 2) gemmG_hmma(
    const __grid_constant__ CUtensorMap tmA,
    const __grid_constant__ CUtensorMap tmB)
{
    extern __shared__ char dsm[];
    __shared__ uint64_t mbar_s[3];
    uint32_t dyn0 = smem_u32(dsm);
    uint32_t smb  = (dyn0 + 1023u) & ~1023u;
    int bk = blockIdx.z;
    int b = bk >> 4, kc = bk & 15;
    int obase = blockIdx.y*128;
    int dbase = blockIdx.x*128;

    float acc[4][4][4];
#pragma unroll
    for (int i = 0; i < 4; i++)
#pragma unroll
        for (int j = 0; j < 4; j++)
#pragma unroll
            for (int r = 0; r < 4; r++) acc[i][j][r] = 0.f;

    gemm_mainloop_tma(&tmA, b*DM + obase, &tmB, b*DI + dbase,
                      kc*CHK, CHK, smb, mbar_s, acc);

    int lane = threadIdx.x & 31, wid = threadIdx.x >> 5;
    int warpM = wid >> 2, warpN = wid & 3;
    int g = lane >> 2, tc = (lane & 3)*2;
    __half* Cg = g_G + (size_t)bk*NE;
#pragma unroll
    for (int mi = 0; mi < 4; mi++)
#pragma unroll
        for (int ni = 0; ni < 4; ni++) {
            int r0  = obase + warpM*64 + mi*16 + g;
            int col = dbase + warpN*32 + ni*8 + tc;
            __half2 v0 = __floats2half2_rn(acc[mi][ni][0]*INV_C, acc[mi][ni][1]*INV_C);
            __half2 v1 = __floats2half2_rn(acc[mi][ni][2]*INV_C, acc[mi][ni][3]*INV_C);
            *(__half2*)(Cg + (size_t)r0*DI + col)     = v0;
            *(__half2*)(Cg + (size_t)(r0+8)*DI + col) = v1;
        }
}

// ---------------- Gram matrix: all 136 pairwise <G_i, G_j> per batch --------
__global__ void __launch_bounds__(128, 1) gram_k() {
    int b = blockIdx.y;
    const __half* Gb = g_G + (size_t)b*NC*NE;
    float acc[NPAIR];
#pragma unroll
    for (int p = 0; p < NPAIR; p++) acc[p] = 0.f;

    for (int e = blockIdx.x*128 + threadIdx.x; e < NE; e += gridDim.x*128) {
        float g[NC];
#pragma unroll
        for (int j = 0; j < NC; j++) g[j] = __half2float(Gb[(size_t)j*NE + e]);
        int p = 0;
#pragma unroll
        for (int j = 0; j < NC; j++)
#pragma unroll
            for (int i = 0; i <= j; i++) { acc[p] = fmaf(g[i], g[j], acc[p]); p++; }
    }
    __shared__ float sw[NPAIR*4];
    int lane = threadIdx.x & 31, w = threadIdx.x >> 5;
#pragma unroll
    for (int p = 0; p < NPAIR; p++) {
        float v = acc[p];
        v += __shfl_xor_sync(0xFFFFFFFFu, v, 16);
        v += __shfl_xor_sync(0xFFFFFFFFu, v, 8);
        v += __shfl_xor_sync(0xFFFFFFFFu, v, 4);
        v += __shfl_xor_sync(0xFFFFFFFFu, v, 2);
        v += __shfl_xor_sync(0xFFFFFFFFu, v, 1);
        if (lane == 0) sw[p*4 + w] = v;
    }
    __syncthreads();
    for (int p = threadIdx.x; p < NPAIR; p += 128)
        atomicAdd(&g_gram[b*NPAIR + p],
                  (double)(sw[p*4] + sw[p*4+1] + sw[p*4+2] + sw[p*4+3]));
}

// ---------------- scalar recursion: sA_k, sB_k from Gram --------------------
__global__ void scal2_k(const float* __restrict__ lil, const float* __restrict__ ldl) {
    int b = threadIdx.x;
    if (b >= B_) return;
    double eta   = exp((double)lil[0]);
    double sg    = 1.0/(1.0 + exp(-(double)ldl[0]));
    double decay = 0.9 + (0.995 - 0.9)*sg;
    double W0n   = sqrt(g_w0n2);
    const double* Gm = g_gram + b*NPAIR;
    double beta[NC];
#pragma unroll
    for (int j = 0; j < NC; j++) beta[j] = 0.0;
    double dwn2 = 0.0;
    for (int k = 0; k < NC; k++) {
        int rb = k*(k+1)/2;
        double gn2 = Gm[rb + k];
        double gsc = fmin(0.02*W0n/(sqrt(gn2) + 1e-8), 1.0);
        double c   = (1.0 - decay)*eta*gsc;
        double dot = 0.0;
        for (int j = 0; j < k; j++) dot += beta[j]*Gm[rb + j];
        double in2 = decay*decay*dwn2 + c*c*gn2 + 2.0*decay*c*dot;
        double s   = fmin(0.1*W0n/(sqrt(in2) + 1e-8), 1.0);
        g_sA[b*NC + k] = (float)(s*decay);
        g_sB[b*NC + k] = (float)(s*c);
        for (int j = 0; j < k; j++) beta[j] *= s*decay;
        beta[k] = s*c;
        dwn2 = in2*s*s;
    }
}

// ---------------- materialize W_k = fp16(W0 + dW_{k-1}) + deltaW ------------
__global__ void matW_k(const float* __restrict__ W0, float* __restrict__ outDW) {
    int b = blockIdx.y;
    __shared__ float sA[NC], sB[NC];
    if (threadIdx.x < NC) { sA[threadIdx.x] = g_sA[b*NC + threadIdx.x];
                            sB[threadIdx.x] = g_sB[b*NC + threadIdx.x]; }
    __syncthreads();
    for (int e = blockIdx.x*blockDim.x + threadIdx.x; e < NE; e += gridDim.x*blockDim.x) {
        float w0 = W0[e];
        float dw = 0.f;
#pragma unroll
        for (int k = 0; k < NC; k++) {
            float w = w0 + dw;
            g_Wh[((size_t)b*NC + k)*NE + e] = __float2half_rn(w);
            float g = __half2float(g_G[((size_t)b*NC + k)*NE + e]);
            dw = fmaf(sA[k], dw, sB[k]*g);
        }
        outDW[(size_t)b*NE + e] = dw;
    }
}

// ---------------- HMMA GEMM (TMA): out = z·W_k^T + bias, split-K2 -----------
__global__ void __launch_bounds__(256, 2) gemmOut_hmma(
    const __grid_constant__ CUtensorMap tmA,
    const __grid_constant__ CUtensorMap tmB,
    const float* __restrict__ bias, float* __restrict__ out)
{
    extern __shared__ char dsm[];
    __shared__ uint64_t mbar_s[3];
    uint32_t dyn0 = smem_u32(dsm);
    uint32_t smb  = (dyn0 + 1023u) & ~1023u;
    int bz = blockIdx.z;
    int bk = bz >> 1, ks = bz & 1;
    int obase = blockIdx.x*128;
    int tbase = blockIdx.y*128;
    const int KH = DI/2;

    float acc[4][4][4];
#pragma unroll
    for (int i = 0; i < 4; i++)
#pragma unroll
        for (int j = 0; j < 4; j++)
#pragma unroll
            for (int r = 0; r < 4; r++) acc[i][j][r] = 0.f;

    gemm_mainloop_tma(&tmA, bk*CHK + tbase, &tmB, bk*DM + obase,
                      ks*KH, KH, smb, mbar_s, acc);

    int lane = threadIdx.x & 31, wid = threadIdx.x >> 5;
    int warpM = wid >> 2, warpN = wid & 3;
    int g = lane >> 2, tc = (lane & 3)*2;
    float* dst = (ks == 0) ? out : g_part;
#pragma unroll
    for (int mi = 0; mi < 4; mi++)
#pragma unroll
        for (int ni = 0; ni < 4; ni++) {
            int r0  = tbase + warpM*64 + mi*16 + g;
            int col = obase + warpN*32 + ni*8 + tc;
            float b0 = 0.f, b1 = 0.f;
            if (ks == 0) { b0 = bias[col]; b1 = bias[col+1]; }
            float2 v0 = make_float2(acc[mi][ni][0] + b0, acc[mi][ni][1] + b1);
            float2 v1 = make_float2(acc[mi][ni][2] + b0, acc[mi][ni][3] + b1);
            *(float2*)(dst + ((size_t)bk*CHK + r0)*DM + col)     = v0;
            *(float2*)(dst + ((size_t)bk*CHK + r0 + 8)*DM + col) = v1;
        }
}

// ---------------- split-K reduce: out += g_part ------------------------------
__global__ void addpart_k(float* __restrict__ out) {
    size_t n4 = (size_t)B_*T_*DM/4;
    float4* o4 = (float4*)out;
    for (size_t i = (size_t)blockIdx.x*blockDim.x + threadIdx.x;
         i < n4; i += (size_t)gridDim.x*blockDim.x) {
        float4 a = o4[i];
        float4 p = ((const float4*)g_part)[i];
        a.x += p.x; a.y += p.y; a.z += p.z; a.w += p.w;
        o4[i] = a;
    }
}

// ---------------- host: tensor map builder (runtime-resolved driver API) ----
typedef CUresult (*EncFn)(CUtensorMap*, CUtensorMapDataType, cuuint32_t, void*,
                          const cuuint64_t*, const cuuint64_t*, const cuuint32_t*,
                          const cuuint32_t*, CUtensorMapInterleave, CUtensorMapSwizzle,
                          CUtensorMapL2promotion, CUtensorMapFloatOOBfill);

static EncFn get_enc() {
    static EncFn fn = nullptr;
    if (!fn) {
        void* p = nullptr;
        cudaDriverEntryPointQueryResult st;
        cudaGetDriverEntryPoint("cuTensorMapEncodeTiled", &p, cudaEnableDefault, &st);
        fn = (EncFn)p;
    }
    return fn;
}

static void enc_map(CUtensorMap* m, void* base, uint64_t klen, uint64_t nrows) {
    cuuint64_t dims[2]    = {klen, nrows};
    cuuint64_t strides[1] = {klen * 2};       // bytes, multiple of 16
    cuuint32_t box[2]     = {64, 128};        // 128B x 128 rows (SW128 atom)
    cuuint32_t es[2]      = {1, 1};
    get_enc()(m, CU_TENSOR_MAP_DATA_TYPE_FLOAT16, 2, base,
        dims, strides, box, es, CU_TENSOR_MAP_INTERLEAVE_NONE,
        CU_TENSOR_MAP_SWIZZLE_128B, CU_TENSOR_MAP_L2_PROMOTION_L2_128B,
        CU_TENSOR_MAP_FLOAT_OOB_FILL_NONE);
}

// ---------------- launch -----------------------------------------------------
extern "C" void kernel_launch(void* const* d_in, const int* in_sizes, int n_in,
                              void* d_out, int out_size) {
    const float* z    = (const float*)d_in[0];
    const float* src  = (const float*)d_in[1];
    const float* W0   = (const float*)d_in[2];
    const float* bias = (const float*)d_in[3];
    const float* cw   = (const float*)d_in[4];
    const float* lil  = (const float*)d_in[5];
    const float* ldl  = (const float*)d_in[6];
    float* out = (float*)d_out;

    cudaFuncSetAttribute(gemmG_hmma,   cudaFuncAttributeMaxDynamicSharedMemorySize, SMEM_DYN);
    cudaFuncSetAttribute(gemmOut_hmma, cudaFuncAttributeMaxDynamicSharedMemorySize, SMEM_DYN);

    // tensor maps (pure host-side; identical every call -> capture-safe)
    void *p_vuT, *p_zuT, *p_zh, *p_Wh;
    cudaGetSymbolAddress(&p_vuT, g_vuT_h);
    cudaGetSymbolAddress(&p_zuT, g_zuT_h);
    cudaGetSymbolAddress(&p_zh,  g_zh);
    cudaGetSymbolAddress(&p_Wh,  g_Wh);
    CUtensorMap tmVu, tmZu, tmZ, tmW;
    enc_map(&tmVu, p_vuT, T_, (uint64_t)B_*DM);
    enc_map(&tmZu, p_zuT, T_, (uint64_t)B_*DI);
    enc_map(&tmZ,  p_zh,  DI, (uint64_t)B_*T_);
    enc_map(&tmW,  p_Wh,  DI, (uint64_t)B_*NC*DM);

    zero_scalars_k<<<2, 256>>>();
    w0norm_k<<<256, 256>>>(W0);
    conv_vu_k<<<B_*T_, 256>>>(src, cw);
    z_rms_k<<<B_*T_, 256>>>(z);
    tsplit_vu_k<<<dim3(DM/32, T_/32, B_), 256>>>();
    tsplit_zu_k<<<dim3(DI/32, T_/32, B_), 256>>>();

    gemmG_hmma<<<dim3(DI/128, DM/128, B_*NC), 256, SMEM_DYN>>>(tmVu, tmZu);

    gram_k<<<dim3(512, B_), 128>>>();
    scal2_k<<<1, 32>>>(lil, ldl);
    matW_k<<<dim3(1024, B_), 256>>>(W0, out + (size_t)B_*T_*DM);

    gemmOut_hmma<<<dim3(DM/128, CHK/128, B_*NC*2), 256, SMEM_DYN>>>(tmZ, tmW, bias, out);
    addpart_k<<<1024, 256>>>(out);
}